// round 9
// baseline (speedup 1.0000x reference)
#include <cuda_runtime.h>

// Gaussian splatting via fine-grained tile-owned gather (8^3 subtiles) with
// globally precomputed per-gaussian exp tables.
// memset node: zero per-tile counters. K2: per-gaussian: compute padded
// 3x32 exp tables (anchored at mn-8, zeros outside bbox, intensity folded
// into z) + bucket scatter. K3: one 64-thread CTA per tile; build = pure
// window gather from global tables into smem (no expf, no predicates),
// single barrier, then scalar scan; volume written exactly once.

#define NT 32
#define NTILES (NT * NT * NT)          // 32768
#define CAP 64
#define NMAX 65536

__device__ int   d_counts[NTILES];
__device__ int   d_bucket[NTILES * CAP];
__device__ int   d_mnpack[NMAX];
__device__ float d_gtab[NMAX * 96];    // [g][axis][32], anchor mn_a - 8

__global__ void scatter_kernel(const float* __restrict__ centers,
                               const float* __restrict__ sigmas,
                               const float* __restrict__ intensities,
                               int n) {
    int g = blockIdx.x * blockDim.x + threadIdx.x;
    if (g >= n) return;

    float c3[3];
    c3[0] = __ldg(&centers[3 * g + 0]);
    c3[1] = __ldg(&centers[3 * g + 1]);
    c3[2] = __ldg(&centers[3 * g + 2]);
    const float sig   = __ldg(&sigmas[g]);
    const float inten = __ldg(&intensities[g]);

    const float cut    = 3.0f * sig * 255.0f;
    const float inv2s2 = 0.5f / (sig * sig);

    int mn[3], mx[3];
#pragma unroll
    for (int a = 0; a < 3; a++) {
        float cv = c3[a] * 255.0f;
        mn[a] = (int)floorf(fmaxf(cv - cut, 0.0f));
        mx[a] = (int)fminf(floorf(fminf(cv + cut, 255.0f)) + 1.0f, 256.0f);
    }

    d_mnpack[g] = mn[0] | (mn[1] << 8) | (mn[2] << 16);

    // Padded exp tables: index i -> voxel mn_a - 8 + i; zero outside bbox.
    float* tg = &d_gtab[g * 96];
#pragma unroll
    for (int a = 0; a < 3; a++) {
        const float c  = c3[a];
        const int   lo = mn[a];
        const int   w  = mx[a] - mn[a];     // bbox width along axis
        const float mul = (a == 2) ? inten : 1.0f;
#pragma unroll 8
        for (int i = 0; i < 32; i++) {
            float v = 0.0f;
            if ((unsigned)(i - 8) < (unsigned)w) {
                float d = (float)(lo - 8 + i) * (1.0f / 255.0f) - c;
                v = mul * __expf(-d * d * inv2s2);
            }
            tg[a * 32 + i] = v;
        }
    }

    const int t0x = mn[0] >> 3, t1x = (mx[0] - 1) >> 3;
    const int t0y = mn[1] >> 3, t1y = (mx[1] - 1) >> 3;
    const int t0z = mn[2] >> 3, t1z = (mx[2] - 1) >> 3;

    for (int tx = t0x; tx <= t1x; tx++)
        for (int ty = t0y; ty <= t1y; ty++)
            for (int tz = t0z; tz <= t1z; tz++) {
                int t = (tx << 10) | (ty << 5) | tz;
                int slot = atomicAdd(&d_counts[t], 1);
                if (slot < CAP) d_bucket[t * CAP + slot] = g;
            }
}

__global__ void __launch_bounds__(64) accum_kernel(float* __restrict__ out) {
    const int t   = blockIdx.x;
    const int tid = threadIdx.x;
    const int ox = (t >> 10) << 3;
    const int oy = ((t >> 5) & 31) << 3;
    const int oz = (t & 31) << 3;

    __shared__ int sbase[CAP];                       // gid * 96
    __shared__ int smn[CAP];                         // packed mn
    __shared__ __align__(16) float sx[CAP * 8];
    __shared__ __align__(16) float sy[CAP * 8];
    __shared__ __align__(16) float sz[CAP * 8];

    int cnt = d_counts[t];
    if (cnt > CAP) cnt = CAP;
    const int bucket_base = t * CAP;

    // Stage gaussian ids + mn packs.
    for (int i = tid; i < cnt; i += 64) {
        int gid = d_bucket[bucket_base + i];
        sbase[i] = gid * 96;
        smn[i]   = d_mnpack[gid];
    }
    __syncthreads();

    const int n8 = cnt * 8;
    // Window gather per axis: slot e = g*8 + i.
    for (int e = tid; e < n8; e += 64) {
        int g = e >> 3, i = e & 7;
        int mnx = smn[g] & 255;
        sx[e] = d_gtab[sbase[g] + (ox - mnx + 8) + i];
    }
    for (int e = tid; e < n8; e += 64) {
        int g = e >> 3, i = e & 7;
        int mny = (smn[g] >> 8) & 255;
        sy[e] = d_gtab[sbase[g] + 32 + (oy - mny + 8) + i];
    }
    for (int e = tid; e < n8; e += 64) {
        int g = e >> 3, i = e & 7;
        int mnz = (smn[g] >> 16) & 255;
        sz[e] = d_gtab[sbase[g] + 64 + (oz - mnz + 8) + i];
    }
    __syncthreads();

    const int xi = tid >> 3;
    const int yi = tid & 7;

    float acc[8];
#pragma unroll
    for (int z = 0; z < 8; z++) acc[z] = 0.0f;

    for (int g = 0; g < cnt; g++) {
        float exy = sx[g * 8 + xi] * sy[g * 8 + yi];
        if (exy != 0.0f) {
            float4 e0 = *(const float4*)&sz[g * 8];
            float4 e1 = *(const float4*)&sz[g * 8 + 4];
            acc[0] = fmaf(exy, e0.x, acc[0]);
            acc[1] = fmaf(exy, e0.y, acc[1]);
            acc[2] = fmaf(exy, e0.z, acc[2]);
            acc[3] = fmaf(exy, e0.w, acc[3]);
            acc[4] = fmaf(exy, e1.x, acc[4]);
            acc[5] = fmaf(exy, e1.y, acc[5]);
            acc[6] = fmaf(exy, e1.z, acc[6]);
            acc[7] = fmaf(exy, e1.w, acc[7]);
        }
    }

    const int addr = (ox + xi) * 65536 + (oy + yi) * 256 + oz;
    *(float4*)&out[addr]     = make_float4(acc[0], acc[1], acc[2], acc[3]);
    *(float4*)&out[addr + 4] = make_float4(acc[4], acc[5], acc[6], acc[7]);
}

extern "C" void kernel_launch(void* const* d_in, const int* in_sizes, int n_in,
                              void* d_out, int out_size) {
    const float* centers = (const float*)d_in[0];
    const float* sigmas = (const float*)d_in[1];
    const float* intensities = (const float*)d_in[2];
    float* out = (float*)d_out;
    const int n = in_sizes[1];

    void* counts_ptr = nullptr;
    cudaGetSymbolAddress(&counts_ptr, d_counts);
    cudaMemsetAsync(counts_ptr, 0, NTILES * sizeof(int), 0);

    scatter_kernel<<<(n + 255) / 256, 256>>>(centers, sigmas, intensities, n);
    accum_kernel<<<NTILES, 64>>>(out);
}

// round 10
// speedup vs baseline: 1.3611x; 1.3611x over previous
#include <cuda_runtime.h>

// Gaussian splatting via tile-owned gather (8x8x16 tiles) with globally
// precomputed per-gaussian exp tables.
//  K0 (memset): zero per-tile counters.
//  K1 bin: per-gaussian bbox -> params + bucket entries {mnpack, gid}.
//  K2 tables: one THREAD PER SLOT builds padded exp tables (coalesced STG,
//     one __expf per thread). Layout per gaussian: x[32] y[32] z[48] = 112.
//     x/y anchored mn-8, z anchored mn-16; zeros outside bbox; intensity
//     folded into z.
//  K3 accum: one 64-thread CTA per tile; window-gather tables into smem
//     (no predicates, guaranteed in-range), single barrier, scalar scan into
//     16 z-registers per thread; volume written exactly once (float4).

#define NTILES 16384                   // 32 x 32 x 16
#define CAP 64
#define NMAX 65536
#define TABW 112

__device__ int    d_counts[NTILES];
__device__ int2   d_bucket[NTILES * CAP];   // {mnpack, gid}
__device__ float4 d_params[2 * NMAX];       // [2g]={cx,cy,cz,inv2s2}; [2g+1]={I, mnpack, wpack, 0}
__device__ float  d_gtab[NMAX * TABW];

__global__ void bin_kernel(const float* __restrict__ centers,
                           const float* __restrict__ sigmas,
                           const float* __restrict__ intensities,
                           int n) {
    int g = blockIdx.x * blockDim.x + threadIdx.x;
    if (g >= n) return;

    float c3[3];
    c3[0] = __ldg(&centers[3 * g + 0]);
    c3[1] = __ldg(&centers[3 * g + 1]);
    c3[2] = __ldg(&centers[3 * g + 2]);
    const float sig   = __ldg(&sigmas[g]);
    const float inten = __ldg(&intensities[g]);

    const float cut    = 3.0f * sig * 255.0f;
    const float inv2s2 = 0.5f / (sig * sig);

    int mn[3], mx[3];
#pragma unroll
    for (int a = 0; a < 3; a++) {
        float cv = c3[a] * 255.0f;
        mn[a] = (int)floorf(fmaxf(cv - cut, 0.0f));
        mx[a] = (int)fminf(floorf(fminf(cv + cut, 255.0f)) + 1.0f, 256.0f);
    }

    int mnp = mn[0] | (mn[1] << 8) | (mn[2] << 16);
    int wp  = (mx[0] - mn[0]) | ((mx[1] - mn[1]) << 8) | ((mx[2] - mn[2]) << 16);

    d_params[2 * g + 0] = make_float4(c3[0], c3[1], c3[2], inv2s2);
    d_params[2 * g + 1] = make_float4(inten, __int_as_float(mnp), __int_as_float(wp), 0.0f);

    const int t0x = mn[0] >> 3, t1x = (mx[0] - 1) >> 3;
    const int t0y = mn[1] >> 3, t1y = (mx[1] - 1) >> 3;
    const int t0z = mn[2] >> 4, t1z = (mx[2] - 1) >> 4;

    int2 entry = make_int2(mnp, g);
    for (int tx = t0x; tx <= t1x; tx++)
        for (int ty = t0y; ty <= t1y; ty++)
            for (int tz = t0z; tz <= t1z; tz++) {
                int t = (tx << 9) | (ty << 4) | tz;
                int slot = atomicAdd(&d_counts[t], 1);
                if (slot < CAP) d_bucket[t * CAP + slot] = entry;
            }
}

__global__ void table_kernel(int n) {
    int e = blockIdx.x * blockDim.x + threadIdx.x;
    int g = e / TABW;
    if (g >= n) return;
    int s = e - g * TABW;

    float4 p0 = d_params[2 * g + 0];
    float4 p1 = d_params[2 * g + 1];

    int a   = (s < 32) ? 0 : ((s < 64) ? 1 : 2);
    int i   = s - ((a == 0) ? 0 : ((a == 1) ? 32 : 64));
    int pad = (a == 2) ? 16 : 8;

    float c = (a == 0) ? p0.x : ((a == 1) ? p0.y : p0.z);
    int mnp = __float_as_int(p1.y);
    int wp  = __float_as_int(p1.z);
    int mn_a = (mnp >> (8 * a)) & 255;
    int w_a  = (wp  >> (8 * a)) & 255;

    float v = 0.0f;
    if ((unsigned)(i - pad) < (unsigned)w_a) {
        float d = (float)(mn_a - pad + i) * (1.0f / 255.0f) - c;
        v = __expf(-d * d * p0.w);
        if (a == 2) v *= p1.x;
    }
    d_gtab[e] = v;
}

__global__ void __launch_bounds__(64) accum_kernel(float* __restrict__ out) {
    const int t   = blockIdx.x;
    const int tid = threadIdx.x;
    const int ox = (t >> 9) << 3;
    const int oy = ((t >> 4) & 31) << 3;
    const int oz = (t & 15) << 4;

    __shared__ int2 sbk[CAP];
    __shared__ __align__(16) float sx[CAP * 8];
    __shared__ __align__(16) float sy[CAP * 8];
    __shared__ __align__(16) float sz[CAP * 16];

    int cnt = d_counts[t];
    if (cnt > CAP) cnt = CAP;
    const int bucket_base = t * CAP;

    for (int i = tid; i < cnt; i += 64)
        sbk[i] = d_bucket[bucket_base + i];
    __syncthreads();

    // Window gathers (all indices guaranteed in-range by table padding).
    const int n8 = cnt * 8;
    for (int e = tid; e < n8; e += 64) {
        int g = e >> 3, i = e & 7;
        int2 bk = sbk[g];
        int base = bk.y * TABW;
        sx[e] = d_gtab[base + (ox - (bk.x & 255) + 8) + i];
    }
    for (int e = tid; e < n8; e += 64) {
        int g = e >> 3, i = e & 7;
        int2 bk = sbk[g];
        int base = bk.y * TABW;
        sy[e] = d_gtab[base + 32 + (oy - ((bk.x >> 8) & 255) + 8) + i];
    }
    const int n16 = cnt * 16;
    for (int e = tid; e < n16; e += 64) {
        int g = e >> 4, i = e & 15;
        int2 bk = sbk[g];
        int base = bk.y * TABW;
        sz[e] = d_gtab[base + 64 + (oz - ((bk.x >> 16) & 255) + 16) + i];
    }
    __syncthreads();

    const int xi = tid >> 3;
    const int yi = tid & 7;

    float acc[16];
#pragma unroll
    for (int z = 0; z < 16; z++) acc[z] = 0.0f;

    for (int g = 0; g < cnt; g++) {
        float exy = sx[g * 8 + xi] * sy[g * 8 + yi];
        if (exy != 0.0f) {
            const float4* ez = (const float4*)&sz[g * 16];
            float4 e0 = ez[0], e1 = ez[1], e2 = ez[2], e3 = ez[3];
            acc[0]  = fmaf(exy, e0.x, acc[0]);
            acc[1]  = fmaf(exy, e0.y, acc[1]);
            acc[2]  = fmaf(exy, e0.z, acc[2]);
            acc[3]  = fmaf(exy, e0.w, acc[3]);
            acc[4]  = fmaf(exy, e1.x, acc[4]);
            acc[5]  = fmaf(exy, e1.y, acc[5]);
            acc[6]  = fmaf(exy, e1.z, acc[6]);
            acc[7]  = fmaf(exy, e1.w, acc[7]);
            acc[8]  = fmaf(exy, e2.x, acc[8]);
            acc[9]  = fmaf(exy, e2.y, acc[9]);
            acc[10] = fmaf(exy, e2.z, acc[10]);
            acc[11] = fmaf(exy, e2.w, acc[11]);
            acc[12] = fmaf(exy, e3.x, acc[12]);
            acc[13] = fmaf(exy, e3.y, acc[13]);
            acc[14] = fmaf(exy, e3.z, acc[14]);
            acc[15] = fmaf(exy, e3.w, acc[15]);
        }
    }

    const int addr = (ox + xi) * 65536 + (oy + yi) * 256 + oz;
    *(float4*)&out[addr]      = make_float4(acc[0],  acc[1],  acc[2],  acc[3]);
    *(float4*)&out[addr + 4]  = make_float4(acc[4],  acc[5],  acc[6],  acc[7]);
    *(float4*)&out[addr + 8]  = make_float4(acc[8],  acc[9],  acc[10], acc[11]);
    *(float4*)&out[addr + 12] = make_float4(acc[12], acc[13], acc[14], acc[15]);
}

extern "C" void kernel_launch(void* const* d_in, const int* in_sizes, int n_in,
                              void* d_out, int out_size) {
    const float* centers = (const float*)d_in[0];
    const float* sigmas = (const float*)d_in[1];
    const float* intensities = (const float*)d_in[2];
    float* out = (float*)d_out;
    const int n = in_sizes[1];

    void* counts_ptr = nullptr;
    cudaGetSymbolAddress(&counts_ptr, d_counts);
    cudaMemsetAsync(counts_ptr, 0, NTILES * sizeof(int), 0);

    bin_kernel<<<(n + 255) / 256, 256>>>(centers, sigmas, intensities, n);
    table_kernel<<<(n * TABW + 255) / 256, 256>>>(n);
    accum_kernel<<<NTILES, 64>>>(out);
}

// round 11
// speedup vs baseline: 1.4359x; 1.0549x over previous
#include <cuda_runtime.h>

// Gaussian splatting via tile-owned gather (8x8x16 tiles) with globally
// precomputed per-gaussian exp tables.
//  K0 (memset): zero per-tile counters.
//  K1 bin: per-gaussian bbox -> params + bucket entries {mnpack, gid};
//     tile loop fully unrolled & predicated (<=18 independent atomics, MLP).
//  K2 tables: one thread per slot builds padded exp tables (coalesced STG).
//     Layout per gaussian: x[32] y[32] z[48] = 112 floats. x/y anchored
//     mn-8, z anchored mn-16; zeros outside bbox; intensity folded into z.
//  K3 accum: one 64-thread CTA per tile; window-gather tables into smem,
//     single barrier, scan with packed f32x2 FMAs into 8 paired z-regs;
//     volume written exactly once (float4 stores).

#define NTILES 16384                   // 32 x 32 x 16
#define CAP 64
#define NMAX 65536
#define TABW 112

__device__ int    d_counts[NTILES];
__device__ int2   d_bucket[NTILES * CAP];   // {mnpack, gid}
__device__ float4 d_params[2 * NMAX];       // [2g]={cx,cy,cz,inv2s2}; [2g+1]={I, mnpack, wpack, 0}
__device__ float  d_gtab[NMAX * TABW];

__device__ __forceinline__ void fma2(unsigned long long& d,
                                     unsigned long long a,
                                     unsigned long long b) {
    asm("fma.rn.f32x2 %0, %1, %2, %0;" : "+l"(d) : "l"(a), "l"(b));
}
__device__ __forceinline__ unsigned long long dup2(float x) {
    unsigned long long r;
    asm("mov.b64 %0, {%1, %1};" : "=l"(r) : "f"(x));
    return r;
}
__device__ __forceinline__ float2 unpack2(unsigned long long v) {
    float2 r;
    asm("mov.b64 {%0, %1}, %2;" : "=f"(r.x), "=f"(r.y) : "l"(v));
    return r;
}

__global__ void __launch_bounds__(128) bin_kernel(
        const float* __restrict__ centers,
        const float* __restrict__ sigmas,
        const float* __restrict__ intensities,
        int n) {
    int g = blockIdx.x * blockDim.x + threadIdx.x;
    if (g >= n) return;

    float c3[3];
    c3[0] = __ldg(&centers[3 * g + 0]);
    c3[1] = __ldg(&centers[3 * g + 1]);
    c3[2] = __ldg(&centers[3 * g + 2]);
    const float sig   = __ldg(&sigmas[g]);
    const float inten = __ldg(&intensities[g]);

    const float cut    = 3.0f * sig * 255.0f;
    const float inv2s2 = 0.5f / (sig * sig);

    int mn[3], mx[3];
#pragma unroll
    for (int a = 0; a < 3; a++) {
        float cv = c3[a] * 255.0f;
        mn[a] = (int)floorf(fmaxf(cv - cut, 0.0f));
        mx[a] = (int)fminf(floorf(fminf(cv + cut, 255.0f)) + 1.0f, 256.0f);
    }

    int mnp = mn[0] | (mn[1] << 8) | (mn[2] << 16);
    int wp  = (mx[0] - mn[0]) | ((mx[1] - mn[1]) << 8) | ((mx[2] - mn[2]) << 16);

    d_params[2 * g + 0] = make_float4(c3[0], c3[1], c3[2], inv2s2);
    d_params[2 * g + 1] = make_float4(inten, __int_as_float(mnp), __int_as_float(wp), 0.0f);

    const int t0x = mn[0] >> 3, nx = ((mx[0] - 1) >> 3) - t0x;   // 0..2
    const int t0y = mn[1] >> 3, ny = ((mx[1] - 1) >> 3) - t0y;   // 0..2
    const int t0z = mn[2] >> 4, nz = ((mx[2] - 1) >> 4) - t0z;   // 0..1

    const int tb = (t0x << 9) | (t0y << 4) | t0z;
    int2 entry = make_int2(mnp, g);

    // Fully unrolled predicated tile loop: independent atomics, full MLP.
#pragma unroll
    for (int dx = 0; dx < 3; dx++)
#pragma unroll
        for (int dy = 0; dy < 3; dy++)
#pragma unroll
            for (int dz = 0; dz < 2; dz++) {
                if (dx <= nx && dy <= ny && dz <= nz) {
                    int t = tb + (dx << 9) + (dy << 4) + dz;
                    int slot = atomicAdd(&d_counts[t], 1);
                    if (slot < CAP) d_bucket[t * CAP + slot] = entry;
                }
            }
}

__global__ void table_kernel(int n) {
    int e = blockIdx.x * blockDim.x + threadIdx.x;
    int g = e / TABW;
    if (g >= n) return;
    int s = e - g * TABW;

    float4 p0 = d_params[2 * g + 0];
    float4 p1 = d_params[2 * g + 1];

    int a   = (s < 32) ? 0 : ((s < 64) ? 1 : 2);
    int i   = s - ((a == 0) ? 0 : ((a == 1) ? 32 : 64));
    int pad = (a == 2) ? 16 : 8;

    float c = (a == 0) ? p0.x : ((a == 1) ? p0.y : p0.z);
    int mnp = __float_as_int(p1.y);
    int wp  = __float_as_int(p1.z);
    int mn_a = (mnp >> (8 * a)) & 255;
    int w_a  = (wp  >> (8 * a)) & 255;

    float v = 0.0f;
    if ((unsigned)(i - pad) < (unsigned)w_a) {
        float d = (float)(mn_a - pad + i) * (1.0f / 255.0f) - c;
        v = __expf(-d * d * p0.w);
        if (a == 2) v *= p1.x;
    }
    d_gtab[e] = v;
}

__global__ void __launch_bounds__(64) accum_kernel(float* __restrict__ out) {
    const int t   = blockIdx.x;
    const int tid = threadIdx.x;
    const int ox = (t >> 9) << 3;
    const int oy = ((t >> 4) & 31) << 3;
    const int oz = (t & 15) << 4;

    __shared__ int2 sbk[CAP];
    __shared__ __align__(16) float sx[CAP * 8];
    __shared__ __align__(16) float sy[CAP * 8];
    __shared__ __align__(16) float sz[CAP * 16];

    int cnt = d_counts[t];
    if (cnt > CAP) cnt = CAP;
    const int bucket_base = t * CAP;

    for (int i = tid; i < cnt; i += 64)
        sbk[i] = d_bucket[bucket_base + i];
    __syncthreads();

    // Window gathers (indices guaranteed in-range by table padding).
    const int n8 = cnt * 8;
    for (int e = tid; e < n8; e += 64) {
        int g = e >> 3, i = e & 7;
        int2 bk = sbk[g];
        int base = bk.y * TABW;
        sx[e] = d_gtab[base + (ox - (bk.x & 255) + 8) + i];
    }
    for (int e = tid; e < n8; e += 64) {
        int g = e >> 3, i = e & 7;
        int2 bk = sbk[g];
        int base = bk.y * TABW;
        sy[e] = d_gtab[base + 32 + (oy - ((bk.x >> 8) & 255) + 8) + i];
    }
    const int n16 = cnt * 16;
    for (int e = tid; e < n16; e += 64) {
        int g = e >> 4, i = e & 15;
        int2 bk = sbk[g];
        int base = bk.y * TABW;
        sz[e] = d_gtab[base + 64 + (oz - ((bk.x >> 16) & 255) + 16) + i];
    }
    __syncthreads();

    const int xi = tid >> 3;
    const int yi = tid & 7;

    unsigned long long acc2[8];
#pragma unroll
    for (int p = 0; p < 8; p++) acc2[p] = 0ULL;

#pragma unroll 2
    for (int g = 0; g < cnt; g++) {
        float exy = sx[g * 8 + xi] * sy[g * 8 + yi];
        if (exy != 0.0f) {
            unsigned long long w2 = dup2(exy);
            const ulonglong2* ez = (const ulonglong2*)&sz[g * 16];
            ulonglong2 a = ez[0], b = ez[1], c = ez[2], d = ez[3];
            fma2(acc2[0], w2, a.x);
            fma2(acc2[1], w2, a.y);
            fma2(acc2[2], w2, b.x);
            fma2(acc2[3], w2, b.y);
            fma2(acc2[4], w2, c.x);
            fma2(acc2[5], w2, c.y);
            fma2(acc2[6], w2, d.x);
            fma2(acc2[7], w2, d.y);
        }
    }

    const int addr = (ox + xi) * 65536 + (oy + yi) * 256 + oz;
#pragma unroll
    for (int q = 0; q < 4; q++) {
        float2 lo = unpack2(acc2[2 * q + 0]);
        float2 hi = unpack2(acc2[2 * q + 1]);
        *(float4*)&out[addr + 4 * q] = make_float4(lo.x, lo.y, hi.x, hi.y);
    }
}

extern "C" void kernel_launch(void* const* d_in, const int* in_sizes, int n_in,
                              void* d_out, int out_size) {
    const float* centers = (const float*)d_in[0];
    const float* sigmas = (const float*)d_in[1];
    const float* intensities = (const float*)d_in[2];
    float* out = (float*)d_out;
    const int n = in_sizes[1];

    void* counts_ptr = nullptr;
    cudaGetSymbolAddress(&counts_ptr, d_counts);
    cudaMemsetAsync(counts_ptr, 0, NTILES * sizeof(int), 0);

    bin_kernel<<<(n + 127) / 128, 128>>>(centers, sigmas, intensities, n);
    table_kernel<<<(n * TABW + 255) / 256, 256>>>(n);
    accum_kernel<<<NTILES, 64>>>(out);
}